// round 14
// baseline (speedup 1.0000x reference)
#include <cuda_runtime.h>
#include <cuda_bf16.h>
#include <mma.h>
#include <math.h>
#include <stdint.h>

using namespace nvcuda;

// Problem constants
#define BB   64
#define NPG  1024
#define FH   128
#define EE   1048576
#define CC   6
#define N0   (BB*NPG)   // 65536
#define KP1  512
#define KP2  256
#define NNN1 (BB*KP1)   // 32768
#define NNN2 (BB*KP2)   // 16384
#define NMASK (N0-1)
#define SLOT 64
#define SMSK (SLOT-1)

// -------- persistent device scratch (only ever referenced from device code) --------
__device__ float g_lin[N0*FH];
__device__ float g_fa[N0*FH];
__device__ float g_score[N0];
__device__ float g_gate1[NNN1];
__device__ float g_gate2[NNN2];
__device__ float g_z[BB*2*FH];
__device__ int   g_cntA[N0];
__device__ int   g_cntB[NNN1];
__device__ int   g_bktA[N0*SLOT];
__device__ int   g_bktB[NNN1*SLOT];
__device__ int   g_map[N0];
__device__ int   g_map2[NNN1];
__device__ int   g_sel1[NNN1];
__device__ int   g_sel2[NNN2];
__device__ __nv_bfloat16 g_wh[3*16384];   // W hi, bf16, [stage][k][n] row-major
__device__ __nv_bfloat16 g_wl[3*16384];   // W lo

__device__ __forceinline__ float bf16_round(float x) {
    return __bfloat162float(__float2bfloat16_rn(x));
}

// ---------------- init ----------------
__global__ void k_init() {
    int i = blockIdx.x * 256 + threadIdx.x;
    g_cntA[i] = 0;
    if (i < NNN1) g_cntB[i] = 0;
    if (i < BB*2*FH) g_z[i] = 0.0f;
}

// ---------------- W prep: W -> bf16 hi/lo, plain [k][n] layout ----------------
__global__ void k_prepw(const float* __restrict__ W1, const float* __restrict__ W2,
                        const float* __restrict__ W3) {
    int idx = blockIdx.x * 256 + threadIdx.x;   // 3*16384 threads
    int stage = idx >> 14;
    int r = idx & 16383;                        // r = k*128+n
    const float* W = (stage == 0) ? W1 : (stage == 1) ? W2 : W3;
    float w = W[r];
    float h = bf16_round(w);
    g_wh[idx] = __float2bfloat16_rn(h);
    g_wl[idx] = __float2bfloat16_rn(w - h);
}

// ---------------- bucket builds ----------------
__global__ void k_build1(const int* __restrict__ ei) {
    int i = blockIdx.x * 256 + threadIdx.x;
    if (i >= EE) return;
    int s = ei[i] & NMASK;
    int d = ei[EE + i] & NMASK;
    int p = atomicAdd(&g_cntA[d], 1) & SMSK;
    g_bktA[((size_t)d << 6) | p] = s;
}
__global__ void k_build2(const int* __restrict__ ei) {
    int i = blockIdx.x * 256 + threadIdx.x;
    if (i < NNN2) g_cntA[i] = 0;
    if (i >= EE) return;
    int s = ei[i] & NMASK;
    int d = ei[EE + i] & NMASK;
    int ns = g_map[s], nd = g_map[d];
    if (ns >= 0 && nd >= 0) {
        int p = atomicAdd(&g_cntB[nd], 1) & SMSK;
        g_bktB[((size_t)nd << 6) | p] = ns;
    }
}
__global__ void k_build3() {
    int idx = blockIdx.x * 256 + threadIdx.x;
    int n2 = idx >> 6, j = idx & SMSK;
    int c = g_cntB[n2]; if (c > SLOT) c = SLOT;
    if (j >= c) return;
    int s2 = g_bktB[((size_t)n2 << 6) | j] & (NNN1 - 1);
    int ns = g_map2[s2], nd = g_map2[n2];
    if (ns >= 0 && nd >= 0) {
        int p = atomicAdd(&g_cntA[nd], 1) & SMSK;
        g_bktA[((size_t)nd << 6) | p] = ns;
    }
}

// ---------------- WMMA bf16x3 GEMM: g_lin[M,128] = A[M,128] @ W[128,128] ----------------
// hi@hi + lo@hi + hi@lo, fp32 acc. 8 warps, each computes 32x64 (mt=2, nt=4).
// GATHER=0: A=Aext; GATHER=1: row=g_fa[sel1]*gate1; GATHER=2: row=g_fa[sel2]*gate2.
template<int GATHER, int STAGE>
__global__ __launch_bounds__(256) void k_gemm_wmma(const float* __restrict__ Aext) {
    const __nv_bfloat16* __restrict__ Wh = g_wh + STAGE * 16384;   // device-side reference
    const __nv_bfloat16* __restrict__ Wl = g_wl + STAGE * 16384;
    __shared__ __nv_bfloat16 Ah[128][32], Al[128][32];   // 8KB each
    __shared__ __nv_bfloat16 Bh[32][128], Bl[32][128];   // 8KB each
    int tid = threadIdx.x;
    int w = tid >> 5;
    int wr = w >> 1, wc = w & 1;             // warp tile: rows [wr*32,+32), cols [wc*64,+64)
    size_t m0 = (size_t)blockIdx.x * 128;

    // A source row: 2 threads per row, 16 floats each per 32-col chunk
    int m = tid >> 1;
    int c0 = (tid & 1) * 16;
    const float* arow;
    float gt = 1.0f;
    if (GATHER == 0) {
        arow = Aext + (m0 + m) * 128;
    } else if (GATHER == 1) {
        int i = (int)(m0 + m) & (NNN1 - 1);
        arow = (const float*)g_fa + ((size_t)(g_sel1[i] & NMASK) << 7);
        gt = g_gate1[i];
    } else {
        int i = (int)(m0 + m) & (NNN2 - 1);
        arow = (const float*)g_fa + ((size_t)(g_sel2[i] & (NNN1 - 1)) << 7);
        gt = g_gate2[i];
    }

    wmma::fragment<wmma::accumulator, 16, 16, 16, float> acc[2][4];
    #pragma unroll
    for (int mt = 0; mt < 2; mt++)
        #pragma unroll
        for (int nt = 0; nt < 4; nt++) wmma::fill_fragment(acc[mt][nt], 0.0f);

    for (int kc = 0; kc < 128; kc += 32) {
        // ---- stage A chunk: fp32 -> bf16 hi/lo (16 floats per thread) ----
        #pragma unroll
        for (int q = 0; q < 4; q++) {
            float4 v = *(const float4*)(arow + kc + c0 + q * 4);
            v.x *= gt; v.y *= gt; v.z *= gt; v.w *= gt;
            float hx = bf16_round(v.x), hy = bf16_round(v.y);
            float hz = bf16_round(v.z), hw = bf16_round(v.w);
            Ah[m][c0 + q*4 + 0] = __float2bfloat16_rn(hx);
            Ah[m][c0 + q*4 + 1] = __float2bfloat16_rn(hy);
            Ah[m][c0 + q*4 + 2] = __float2bfloat16_rn(hz);
            Ah[m][c0 + q*4 + 3] = __float2bfloat16_rn(hw);
            Al[m][c0 + q*4 + 0] = __float2bfloat16_rn(v.x - hx);
            Al[m][c0 + q*4 + 1] = __float2bfloat16_rn(v.y - hy);
            Al[m][c0 + q*4 + 2] = __float2bfloat16_rn(v.z - hz);
            Al[m][c0 + q*4 + 3] = __float2bfloat16_rn(v.w - hw);
        }
        // ---- stage B chunk: 32x128 hi/lo, contiguous uint4 copies ----
        #pragma unroll
        for (int it = 0; it < 2; it++) {
            int idx = tid * 8 + it * 2048;
            int bk = idx >> 7, bn = idx & 127;
            *(uint4*)&Bh[bk][bn] = *(const uint4*)(Wh + (size_t)(kc + bk) * 128 + bn);
            *(uint4*)&Bl[bk][bn] = *(const uint4*)(Wl + (size_t)(kc + bk) * 128 + bn);
        }
        __syncthreads();

        #pragma unroll
        for (int ks = 0; ks < 32; ks += 16) {
            wmma::fragment<wmma::matrix_a, 16, 16, 16, __nv_bfloat16, wmma::row_major> ah[2], al[2];
            #pragma unroll
            for (int mt = 0; mt < 2; mt++) {
                wmma::load_matrix_sync(ah[mt], &Ah[wr * 32 + mt * 16][ks], 32);
                wmma::load_matrix_sync(al[mt], &Al[wr * 32 + mt * 16][ks], 32);
            }
            #pragma unroll
            for (int nt = 0; nt < 4; nt++) {
                wmma::fragment<wmma::matrix_b, 16, 16, 16, __nv_bfloat16, wmma::row_major> bh, bl;
                wmma::load_matrix_sync(bh, &Bh[ks][wc * 64 + nt * 16], 128);
                wmma::load_matrix_sync(bl, &Bl[ks][wc * 64 + nt * 16], 128);
                #pragma unroll
                for (int mt = 0; mt < 2; mt++) {
                    wmma::mma_sync(acc[mt][nt], ah[mt], bh, acc[mt][nt]);
                    wmma::mma_sync(acc[mt][nt], al[mt], bh, acc[mt][nt]);
                    wmma::mma_sync(acc[mt][nt], ah[mt], bl, acc[mt][nt]);
                }
            }
        }
        __syncthreads();
    }

    #pragma unroll
    for (int mt = 0; mt < 2; mt++)
        #pragma unroll
        for (int nt = 0; nt < 4; nt++)
            wmma::store_matrix_sync(g_lin + (m0 + wr * 32 + mt * 16) * 128 + wc * 64 + nt * 16,
                                    acc[mt][nt], 128, wmma::mem_row_major);
}

// ---------------- GCN conv: aggregate + bias + score + relu (warp/node) ----------------
template<int WHICH>
__global__ void k_conv(const float* __restrict__ bias,
                       const float* __restrict__ ws,
                       int nnodes) {
    int warp = (blockIdx.x * blockDim.x + threadIdx.x) >> 5;
    int lane = threadIdx.x & 31;
    if (warp >= nnodes) return;
    int node = warp;
    const int* cnt = WHICH ? g_cntB : g_cntA;
    const int* bkt = WHICH ? g_bktB : g_bktA;
    int c = cnt[node]; if (c > SLOT) c = SLOT;
    float degd = (float)c + 1.0f;
    float rsd  = rsqrtf(degd);
    size_t base = (size_t)node << 6;
    float4 acc = make_float4(0.f, 0.f, 0.f, 0.f);

    for (int b = 0; b < c; b += 32) {
        int m = c - b; if (m > 32) m = 32;
        int  src = 0; float nrm = 0.f;
        if (lane < m) {
            src = bkt[base + b + lane] & NMASK;
            int cs = cnt[src]; if (cs > SLOT) cs = SLOT;
            nrm = rsd * rsqrtf((float)cs + 1.0f);
        }
        for (int e = 0; e < m; e++) {
            int   s  = __shfl_sync(0xffffffffu, src, e);
            float nm = __shfl_sync(0xffffffffu, nrm, e);
            float4 hv = *(const float4*)(g_lin + ((size_t)s << 7) + (lane << 2));
            acc.x += hv.x * nm; acc.y += hv.y * nm;
            acc.z += hv.z * nm; acc.w += hv.w * nm;
        }
    }
    float dinv = 1.0f / degd;
    float4 self = *(const float4*)(g_lin + ((size_t)node << 7) + (lane << 2));
    float4 bv   = *(const float4*)(bias + (lane << 2));
    float o0 = acc.x + self.x * dinv + bv.x;
    float o1 = acc.y + self.y * dinv + bv.y;
    float o2 = acc.z + self.z * dinv + bv.z;
    float o3 = acc.w + self.w * dinv + bv.w;
    float4 wv = *(const float4*)(ws + (lane << 2));
    float sc = o0 * wv.x + o1 * wv.y + o2 * wv.z + o3 * wv.w;
    #pragma unroll
    for (int off = 16; off; off >>= 1) sc += __shfl_xor_sync(0xffffffffu, sc, off);
    if (lane == 0) g_score[node] = sc;
    float4 r = make_float4(fmaxf(o0, 0.f), fmaxf(o1, 0.f), fmaxf(o2, 0.f), fmaxf(o3, 0.f));
    *(float4*)(g_fa + ((size_t)node << 7) + (lane << 2)) = r;
}

// ---------------- per-graph top-k via bitonic sort ----------------
template<int STAGE>
__global__ void k_topk(int n, int k) {
    __shared__ float s[1024];
    __shared__ int   id[1024];
    int g = blockIdx.x & (BB - 1);
    int half = n >> 1;
    int t = threadIdx.x & (half - 1);
    s[t] = g_score[(g * n + t) & NMASK];               id[t] = t;
    s[t + half] = g_score[(g * n + t + half) & NMASK]; id[t + half] = t + half;
    __syncthreads();
    for (int kk = 2; kk <= n; kk <<= 1) {
        for (int j = kk >> 1; j > 0; j >>= 1) {
            int i = ((t & ~(j - 1)) << 1) | (t & (j - 1));
            int p = i | j;
            bool up = ((i & kk) == 0);
            float a = s[i], b = s[p];
            if ((a > b) == up) {
                s[i] = b; s[p] = a;
                int tmp = id[i]; id[i] = id[p]; id[p] = tmp;
            }
            __syncthreads();
        }
    }
    for (int p = t; p < n; p += half) {
        int oldl = id[p] & (n - 1);
        int ng = -1;
        if (p >= n - k) {
            int j = n - 1 - p;
            ng = g * k + j;
            if (STAGE == 0) {
                g_sel1[ng & (NNN1-1)]  = g * n + oldl;
                g_gate1[ng & (NNN1-1)] = tanhf(s[p]);
            } else {
                g_sel2[ng & (NNN2-1)]  = g * n + oldl;
                g_gate2[ng & (NNN2-1)] = tanhf(s[p]);
            }
        }
        if (STAGE == 0) g_map[(g * n + oldl) & NMASK] = ng;
        else            g_map2[(g * n + oldl) & (NNN1-1)] = ng;
    }
}

// ---------------- readout with inline gather ----------------
template<int STAGE>
__global__ void k_readout(int k) {
    int g = blockIdx.x & (BB - 1), f = threadIdx.x & 127;
    float mx = -3.4e38f, sm = 0.f;
    for (int m = 0; m < k; m++) {
        float v;
        if (STAGE == 1) {
            int i = g * k + m;
            v = g_fa[((size_t)(g_sel1[i] & NMASK) << 7) + f] * g_gate1[i];
        } else if (STAGE == 2) {
            int i = g * k + m;
            v = g_fa[((size_t)(g_sel2[i] & (NNN1-1)) << 7) + f] * g_gate2[i];
        } else {
            v = g_fa[((size_t)(g * k + m) << 7) + f];
        }
        mx = fmaxf(mx, v);
        sm += v;
    }
    g_z[g * 256 + f]       += fmaxf(mx, 0.f);
    g_z[g * 256 + 128 + f] += fmaxf(sm * (1.0f / (float)k), 0.f);
}

// ---------------- MLP head + log_softmax ----------------
__global__ void k_mlp(const float* __restrict__ L1w, const float* __restrict__ L1b,
                      const float* __restrict__ L2w, const float* __restrict__ L2b,
                      const float* __restrict__ L3w, const float* __restrict__ L3b,
                      float* __restrict__ out) {
    int g = blockIdx.x & (BB - 1), t = threadIdx.x & 127;
    __shared__ float zr[256], y1[128], y2[64], y3[8], lse[1];
    zr[t]       = g_z[g * 256 + t];
    zr[t + 128] = g_z[g * 256 + 128 + t];
    __syncthreads();
    float a = L1b[t];
    for (int i = 0; i < 256; i++) a += zr[i] * L1w[i * 128 + t];
    y1[t] = fmaxf(a, 0.f);
    __syncthreads();
    if (t < 64) {
        float b = L2b[t];
        for (int i = 0; i < 128; i++) b += y1[i] * L2w[i * 64 + t];
        y2[t] = fmaxf(b, 0.f);
    }
    __syncthreads();
    if (t < CC) {
        float c = L3b[t];
        for (int i = 0; i < 64; i++) c += y2[i] * L3w[i * CC + t];
        y3[t] = c;
    }
    __syncthreads();
    if (t == 0) {
        float m = y3[0];
        for (int j = 1; j < CC; j++) m = fmaxf(m, y3[j]);
        float s = 0.f;
        for (int j = 0; j < CC; j++) s += expf(y3[j] - m);
        lse[0] = m + logf(s);
    }
    __syncthreads();
    if (t < CC) out[g * CC + t] = y3[t] - lse[0];
}

// ======================================================================
extern "C" void kernel_launch(void* const* d_in, const int* in_sizes, int n_in,
                              void* d_out, int out_size) {
    const float* x    = (const float*)d_in[0];
    const int*   ei32 = (const int*)d_in[1];
    const float* W1 = (const float*)d_in[3];
    const float* b1 = (const float*)d_in[4];
    const float* s1 = (const float*)d_in[5];
    const float* W2 = (const float*)d_in[6];
    const float* b2 = (const float*)d_in[7];
    const float* s2 = (const float*)d_in[8];
    const float* W3 = (const float*)d_in[9];
    const float* b3 = (const float*)d_in[10];
    const float* s3 = (const float*)d_in[11];
    const float* L1w = (const float*)d_in[12];
    const float* L1b = (const float*)d_in[13];
    const float* L2w = (const float*)d_in[14];
    const float* L2b = (const float*)d_in[15];
    const float* L3w = (const float*)d_in[16];
    const float* L3b = (const float*)d_in[17];
    float* out = (float*)d_out;

    k_init<<<256, 256>>>();
    k_prepw<<<192, 256>>>(W1, W2, W3);

    // ---- stage 1 ----
    k_build1<<<EE/256, 256>>>(ei32);
    k_gemm_wmma<0, 0><<<N0/128, 256>>>(x);
    k_conv<0><<<N0/8, 256>>>(b1, s1, N0);
    k_topk<0><<<BB, NPG/2>>>(NPG, KP1);
    k_readout<1><<<BB, 128>>>(KP1);

    // ---- stage 2 ----
    k_build2<<<EE/256, 256>>>(ei32);
    k_gemm_wmma<1, 1><<<NNN1/128, 256>>>(nullptr);
    k_conv<1><<<NNN1/8, 256>>>(b2, s2, NNN1);
    k_topk<1><<<BB, KP1/2>>>(KP1, KP2);
    k_readout<2><<<BB, 128>>>(KP2);

    // ---- stage 3 ----
    k_build3<<<(NNN1*SLOT)/256, 256>>>();
    k_gemm_wmma<2, 2><<<NNN2/128, 256>>>(nullptr);
    k_conv<0><<<NNN2/8, 256>>>(b3, s3, NNN2);
    k_readout<3><<<BB, 128>>>(KP2);

    // ---- head ----
    k_mlp<<<BB, 128>>>(L1w, L1b, L2w, L2b, L3w, L3b, out);
}

// round 15
// speedup vs baseline: 1.0644x; 1.0644x over previous
#include <cuda_runtime.h>
#include <cuda_bf16.h>
#include <mma.h>
#include <math.h>
#include <stdint.h>

using namespace nvcuda;

// Problem constants
#define BB   64
#define NPG  1024
#define FH   128
#define EE   1048576
#define CC   6
#define N0   (BB*NPG)   // 65536
#define KP1  512
#define KP2  256
#define NNN1 (BB*KP1)   // 32768
#define NNN2 (BB*KP2)   // 16384
#define NMASK (N0-1)
#define SLOT 64
#define SMSK (SLOT-1)

// -------- persistent device scratch (only ever referenced from device code) --------
__device__ float g_lin[N0*FH];
__device__ float g_fa[N0*FH];
__device__ float g_score[N0];
__device__ float g_gate1[NNN1];
__device__ float g_gate2[NNN2];
__device__ float g_z[BB*2*FH];
__device__ int   g_cntA[N0];
__device__ int   g_cntB[NNN1];
__device__ int   g_bktA[N0*SLOT];
__device__ int   g_bktB[NNN1*SLOT];
__device__ int   g_map[N0];
__device__ int   g_map2[NNN1];
__device__ int   g_sel1[NNN1];
__device__ int   g_sel2[NNN2];
__device__ __nv_bfloat16 g_wh[3*16384];   // W hi, bf16, [stage][k][n] row-major
__device__ __nv_bfloat16 g_wl[3*16384];   // W lo

__device__ __forceinline__ float bf16_round(float x) {
    return __bfloat162float(__float2bfloat16_rn(x));
}

// ---------------- init ----------------
__global__ void k_init() {
    int i = blockIdx.x * 256 + threadIdx.x;
    g_cntA[i] = 0;
    if (i < NNN1) g_cntB[i] = 0;
    if (i < BB*2*FH) g_z[i] = 0.0f;
}

// ---------------- W prep: W -> bf16 hi/lo, plain [k][n] layout ----------------
__global__ void k_prepw(const float* __restrict__ W1, const float* __restrict__ W2,
                        const float* __restrict__ W3) {
    int idx = blockIdx.x * 256 + threadIdx.x;   // 3*16384 threads
    int stage = idx >> 14;
    int r = idx & 16383;                        // r = k*128+n
    const float* W = (stage == 0) ? W1 : (stage == 1) ? W2 : W3;
    float w = W[r];
    float h = bf16_round(w);
    g_wh[idx] = __float2bfloat16_rn(h);
    g_wl[idx] = __float2bfloat16_rn(w - h);
}

// ---------------- bucket builds ----------------
__global__ void k_build1(const int* __restrict__ ei) {
    int i = blockIdx.x * 256 + threadIdx.x;
    if (i >= EE) return;
    int s = ei[i] & NMASK;
    int d = ei[EE + i] & NMASK;
    int p = atomicAdd(&g_cntA[d], 1) & SMSK;
    g_bktA[((size_t)d << 6) | p] = s;
}
__global__ void k_build2(const int* __restrict__ ei) {
    int i = blockIdx.x * 256 + threadIdx.x;
    if (i < NNN2) g_cntA[i] = 0;
    if (i >= EE) return;
    int s = ei[i] & NMASK;
    int d = ei[EE + i] & NMASK;
    int ns = g_map[s], nd = g_map[d];
    if (ns >= 0 && nd >= 0) {
        int p = atomicAdd(&g_cntB[nd], 1) & SMSK;
        g_bktB[((size_t)nd << 6) | p] = ns;
    }
}
__global__ void k_build3() {
    int idx = blockIdx.x * 256 + threadIdx.x;
    int n2 = idx >> 6, j = idx & SMSK;
    int c = g_cntB[n2]; if (c > SLOT) c = SLOT;
    if (j >= c) return;
    int s2 = g_bktB[((size_t)n2 << 6) | j] & (NNN1 - 1);
    int ns = g_map2[s2], nd = g_map2[n2];
    if (ns >= 0 && nd >= 0) {
        int p = atomicAdd(&g_cntA[nd], 1) & SMSK;
        g_bktA[((size_t)nd << 6) | p] = ns;
    }
}

// ---------------- WMMA bf16x3 GEMM: g_lin[M,128] = A[M,128] @ W[128,128] ----------------
// hi@hi + lo@hi + hi@lo, fp32 acc. 4 warps, each computes 64x64 (mt=4, nt=4).
// Two sub-passes per k16 share ONE a-fragment array -> no register spills.
// GATHER=0: A=Aext; GATHER=1: row=g_fa[sel1]*gate1; GATHER=2: row=g_fa[sel2]*gate2.
template<int GATHER, int STAGE>
__global__ __launch_bounds__(128) void k_gemm_wmma(const float* __restrict__ Aext) {
    const __nv_bfloat16* __restrict__ Wh = g_wh + STAGE * 16384;   // device-side reference
    const __nv_bfloat16* __restrict__ Wl = g_wl + STAGE * 16384;
    __shared__ __nv_bfloat16 Ah[128][32], Al[128][32];   // 8KB each
    __shared__ __nv_bfloat16 Bh[32][128], Bl[32][128];   // 8KB each
    int tid = threadIdx.x;
    int w = tid >> 5;
    int wr = w >> 1, wc = w & 1;             // warp tile: rows [wr*64,+64), cols [wc*64,+64)
    size_t m0 = (size_t)blockIdx.x * 128;

    // A source row: one row per thread (32 floats per k-chunk)
    int m = tid;
    const float* arow;
    float gt = 1.0f;
    if (GATHER == 0) {
        arow = Aext + (m0 + m) * 128;
    } else if (GATHER == 1) {
        int i = (int)(m0 + m) & (NNN1 - 1);
        arow = (const float*)g_fa + ((size_t)(g_sel1[i] & NMASK) << 7);
        gt = g_gate1[i];
    } else {
        int i = (int)(m0 + m) & (NNN2 - 1);
        arow = (const float*)g_fa + ((size_t)(g_sel2[i] & (NNN1 - 1)) << 7);
        gt = g_gate2[i];
    }

    wmma::fragment<wmma::accumulator, 16, 16, 16, float> acc[4][4];
    #pragma unroll
    for (int mt = 0; mt < 4; mt++)
        #pragma unroll
        for (int nt = 0; nt < 4; nt++) wmma::fill_fragment(acc[mt][nt], 0.0f);

    for (int kc = 0; kc < 128; kc += 32) {
        // ---- stage A chunk: fp32 -> bf16 hi/lo (32 floats per thread) ----
        #pragma unroll
        for (int q = 0; q < 8; q++) {
            float4 v = *(const float4*)(arow + kc + q * 4);
            v.x *= gt; v.y *= gt; v.z *= gt; v.w *= gt;
            float hx = bf16_round(v.x), hy = bf16_round(v.y);
            float hz = bf16_round(v.z), hw = bf16_round(v.w);
            Ah[m][q*4 + 0] = __float2bfloat16_rn(hx);
            Ah[m][q*4 + 1] = __float2bfloat16_rn(hy);
            Ah[m][q*4 + 2] = __float2bfloat16_rn(hz);
            Ah[m][q*4 + 3] = __float2bfloat16_rn(hw);
            Al[m][q*4 + 0] = __float2bfloat16_rn(v.x - hx);
            Al[m][q*4 + 1] = __float2bfloat16_rn(v.y - hy);
            Al[m][q*4 + 2] = __float2bfloat16_rn(v.z - hz);
            Al[m][q*4 + 3] = __float2bfloat16_rn(v.w - hw);
        }
        // ---- stage B chunk: 32x128 hi/lo, contiguous uint4 copies ----
        #pragma unroll
        for (int it = 0; it < 4; it++) {
            int idx = tid * 8 + it * 1024;
            int bk = idx >> 7, bn = idx & 127;
            *(uint4*)&Bh[bk][bn] = *(const uint4*)(Wh + (size_t)(kc + bk) * 128 + bn);
            *(uint4*)&Bl[bk][bn] = *(const uint4*)(Wl + (size_t)(kc + bk) * 128 + bn);
        }
        __syncthreads();

        #pragma unroll
        for (int ks = 0; ks < 32; ks += 16) {
            wmma::fragment<wmma::matrix_a, 16, 16, 16, __nv_bfloat16, wmma::row_major> af[4];
            // ---- sub-pass 1: a_hi @ (b_hi, b_lo) ----
            #pragma unroll
            for (int mt = 0; mt < 4; mt++)
                wmma::load_matrix_sync(af[mt], &Ah[wr * 64 + mt * 16][ks], 32);
            #pragma unroll
            for (int nt = 0; nt < 4; nt++) {
                wmma::fragment<wmma::matrix_b, 16, 16, 16, __nv_bfloat16, wmma::row_major> bh, bl;
                wmma::load_matrix_sync(bh, &Bh[ks][wc * 64 + nt * 16], 128);
                wmma::load_matrix_sync(bl, &Bl[ks][wc * 64 + nt * 16], 128);
                #pragma unroll
                for (int mt = 0; mt < 4; mt++) {
                    wmma::mma_sync(acc[mt][nt], af[mt], bh, acc[mt][nt]);
                    wmma::mma_sync(acc[mt][nt], af[mt], bl, acc[mt][nt]);
                }
            }
            // ---- sub-pass 2: a_lo @ b_hi (reuse af registers) ----
            #pragma unroll
            for (int mt = 0; mt < 4; mt++)
                wmma::load_matrix_sync(af[mt], &Al[wr * 64 + mt * 16][ks], 32);
            #pragma unroll
            for (int nt = 0; nt < 4; nt++) {
                wmma::fragment<wmma::matrix_b, 16, 16, 16, __nv_bfloat16, wmma::row_major> bh;
                wmma::load_matrix_sync(bh, &Bh[ks][wc * 64 + nt * 16], 128);
                #pragma unroll
                for (int mt = 0; mt < 4; mt++)
                    wmma::mma_sync(acc[mt][nt], af[mt], bh, acc[mt][nt]);
            }
        }
        __syncthreads();
    }

    #pragma unroll
    for (int mt = 0; mt < 4; mt++)
        #pragma unroll
        for (int nt = 0; nt < 4; nt++)
            wmma::store_matrix_sync(g_lin + (m0 + wr * 64 + mt * 16) * 128 + wc * 64 + nt * 16,
                                    acc[mt][nt], 128, wmma::mem_row_major);
}

// ---------------- GCN conv: aggregate + bias + score + relu (warp/node) ----------------
template<int WHICH>
__global__ void k_conv(const float* __restrict__ bias,
                       const float* __restrict__ ws,
                       int nnodes) {
    int warp = (blockIdx.x * blockDim.x + threadIdx.x) >> 5;
    int lane = threadIdx.x & 31;
    if (warp >= nnodes) return;
    int node = warp;
    const int* cnt = WHICH ? g_cntB : g_cntA;
    const int* bkt = WHICH ? g_bktB : g_bktA;
    int c = cnt[node]; if (c > SLOT) c = SLOT;
    float degd = (float)c + 1.0f;
    float rsd  = rsqrtf(degd);
    size_t base = (size_t)node << 6;
    float4 acc = make_float4(0.f, 0.f, 0.f, 0.f);

    for (int b = 0; b < c; b += 32) {
        int m = c - b; if (m > 32) m = 32;
        int  src = 0; float nrm = 0.f;
        if (lane < m) {
            src = bkt[base + b + lane] & NMASK;
            int cs = cnt[src]; if (cs > SLOT) cs = SLOT;
            nrm = rsd * rsqrtf((float)cs + 1.0f);
        }
        for (int e = 0; e < m; e++) {
            int   s  = __shfl_sync(0xffffffffu, src, e);
            float nm = __shfl_sync(0xffffffffu, nrm, e);
            float4 hv = *(const float4*)(g_lin + ((size_t)s << 7) + (lane << 2));
            acc.x += hv.x * nm; acc.y += hv.y * nm;
            acc.z += hv.z * nm; acc.w += hv.w * nm;
        }
    }
    float dinv = 1.0f / degd;
    float4 self = *(const float4*)(g_lin + ((size_t)node << 7) + (lane << 2));
    float4 bv   = *(const float4*)(bias + (lane << 2));
    float o0 = acc.x + self.x * dinv + bv.x;
    float o1 = acc.y + self.y * dinv + bv.y;
    float o2 = acc.z + self.z * dinv + bv.z;
    float o3 = acc.w + self.w * dinv + bv.w;
    float4 wv = *(const float4*)(ws + (lane << 2));
    float sc = o0 * wv.x + o1 * wv.y + o2 * wv.z + o3 * wv.w;
    #pragma unroll
    for (int off = 16; off; off >>= 1) sc += __shfl_xor_sync(0xffffffffu, sc, off);
    if (lane == 0) g_score[node] = sc;
    float4 r = make_float4(fmaxf(o0, 0.f), fmaxf(o1, 0.f), fmaxf(o2, 0.f), fmaxf(o3, 0.f));
    *(float4*)(g_fa + ((size_t)node << 7) + (lane << 2)) = r;
}

// ---------------- per-graph top-k via bitonic sort ----------------
template<int STAGE>
__global__ void k_topk(int n, int k) {
    __shared__ float s[1024];
    __shared__ int   id[1024];
    int g = blockIdx.x & (BB - 1);
    int half = n >> 1;
    int t = threadIdx.x & (half - 1);
    s[t] = g_score[(g * n + t) & NMASK];               id[t] = t;
    s[t + half] = g_score[(g * n + t + half) & NMASK]; id[t + half] = t + half;
    __syncthreads();
    for (int kk = 2; kk <= n; kk <<= 1) {
        for (int j = kk >> 1; j > 0; j >>= 1) {
            int i = ((t & ~(j - 1)) << 1) | (t & (j - 1));
            int p = i | j;
            bool up = ((i & kk) == 0);
            float a = s[i], b = s[p];
            if ((a > b) == up) {
                s[i] = b; s[p] = a;
                int tmp = id[i]; id[i] = id[p]; id[p] = tmp;
            }
            __syncthreads();
        }
    }
    for (int p = t; p < n; p += half) {
        int oldl = id[p] & (n - 1);
        int ng = -1;
        if (p >= n - k) {
            int j = n - 1 - p;
            ng = g * k + j;
            if (STAGE == 0) {
                g_sel1[ng & (NNN1-1)]  = g * n + oldl;
                g_gate1[ng & (NNN1-1)] = tanhf(s[p]);
            } else {
                g_sel2[ng & (NNN2-1)]  = g * n + oldl;
                g_gate2[ng & (NNN2-1)] = tanhf(s[p]);
            }
        }
        if (STAGE == 0) g_map[(g * n + oldl) & NMASK] = ng;
        else            g_map2[(g * n + oldl) & (NNN1-1)] = ng;
    }
}

// ---------------- readout with inline gather ----------------
template<int STAGE>
__global__ void k_readout(int k) {
    int g = blockIdx.x & (BB - 1), f = threadIdx.x & 127;
    float mx = -3.4e38f, sm = 0.f;
    for (int m = 0; m < k; m++) {
        float v;
        if (STAGE == 1) {
            int i = g * k + m;
            v = g_fa[((size_t)(g_sel1[i] & NMASK) << 7) + f] * g_gate1[i];
        } else if (STAGE == 2) {
            int i = g * k + m;
            v = g_fa[((size_t)(g_sel2[i] & (NNN1-1)) << 7) + f] * g_gate2[i];
        } else {
            v = g_fa[((size_t)(g * k + m) << 7) + f];
        }
        mx = fmaxf(mx, v);
        sm += v;
    }
    g_z[g * 256 + f]       += fmaxf(mx, 0.f);
    g_z[g * 256 + 128 + f] += fmaxf(sm * (1.0f / (float)k), 0.f);
}

// ---------------- MLP head + log_softmax ----------------
__global__ void k_mlp(const float* __restrict__ L1w, const float* __restrict__ L1b,
                      const float* __restrict__ L2w, const float* __restrict__ L2b,
                      const float* __restrict__ L3w, const float* __restrict__ L3b,
                      float* __restrict__ out) {
    int g = blockIdx.x & (BB - 1), t = threadIdx.x & 127;
    __shared__ float zr[256], y1[128], y2[64], y3[8], lse[1];
    zr[t]       = g_z[g * 256 + t];
    zr[t + 128] = g_z[g * 256 + 128 + t];
    __syncthreads();
    float a = L1b[t];
    for (int i = 0; i < 256; i++) a += zr[i] * L1w[i * 128 + t];
    y1[t] = fmaxf(a, 0.f);
    __syncthreads();
    if (t < 64) {
        float b = L2b[t];
        for (int i = 0; i < 128; i++) b += y1[i] * L2w[i * 64 + t];
        y2[t] = fmaxf(b, 0.f);
    }
    __syncthreads();
    if (t < CC) {
        float c = L3b[t];
        for (int i = 0; i < 64; i++) c += y2[i] * L3w[i * CC + t];
        y3[t] = c;
    }
    __syncthreads();
    if (t == 0) {
        float m = y3[0];
        for (int j = 1; j < CC; j++) m = fmaxf(m, y3[j]);
        float s = 0.f;
        for (int j = 0; j < CC; j++) s += expf(y3[j] - m);
        lse[0] = m + logf(s);
    }
    __syncthreads();
    if (t < CC) out[g * CC + t] = y3[t] - lse[0];
}

// ======================================================================
extern "C" void kernel_launch(void* const* d_in, const int* in_sizes, int n_in,
                              void* d_out, int out_size) {
    const float* x    = (const float*)d_in[0];
    const int*   ei32 = (const int*)d_in[1];
    const float* W1 = (const float*)d_in[3];
    const float* b1 = (const float*)d_in[4];
    const float* s1 = (const float*)d_in[5];
    const float* W2 = (const float*)d_in[6];
    const float* b2 = (const float*)d_in[7];
    const float* s2 = (const float*)d_in[8];
    const float* W3 = (const float*)d_in[9];
    const float* b3 = (const float*)d_in[10];
    const float* s3 = (const float*)d_in[11];
    const float* L1w = (const float*)d_in[12];
    const float* L1b = (const float*)d_in[13];
    const float* L2w = (const float*)d_in[14];
    const float* L2b = (const float*)d_in[15];
    const float* L3w = (const float*)d_in[16];
    const float* L3b = (const float*)d_in[17];
    float* out = (float*)d_out;

    k_init<<<256, 256>>>();
    k_prepw<<<192, 256>>>(W1, W2, W3);

    // ---- stage 1 ----
    k_build1<<<EE/256, 256>>>(ei32);
    k_gemm_wmma<0, 0><<<N0/128, 128>>>(x);
    k_conv<0><<<N0/8, 256>>>(b1, s1, N0);
    k_topk<0><<<BB, NPG/2>>>(NPG, KP1);
    k_readout<1><<<BB, 128>>>(KP1);

    // ---- stage 2 ----
    k_build2<<<EE/256, 256>>>(ei32);
    k_gemm_wmma<1, 1><<<NNN1/128, 128>>>(nullptr);
    k_conv<1><<<NNN1/8, 256>>>(b2, s2, NNN1);
    k_topk<1><<<BB, KP1/2>>>(KP1, KP2);
    k_readout<2><<<BB, 128>>>(KP2);

    // ---- stage 3 ----
    k_build3<<<(NNN1*SLOT)/256, 256>>>();
    k_gemm_wmma<2, 2><<<NNN2/128, 128>>>(nullptr);
    k_conv<0><<<NNN2/8, 256>>>(b3, s3, NNN2);
    k_readout<3><<<BB, 128>>>(KP2);

    // ---- head ----
    k_mlp<<<BB, 128>>>(L1w, L1b, L2w, L2b, L3w, L3b, out);
}

// round 16
// speedup vs baseline: 1.2182x; 1.1444x over previous
#include <cuda_runtime.h>
#include <cuda_bf16.h>
#include <mma.h>
#include <math.h>
#include <stdint.h>

using namespace nvcuda;

// Problem constants
#define BB   64
#define NPG  1024
#define FH   128
#define EE   1048576
#define CC   6
#define N0   (BB*NPG)   // 65536
#define KP1  512
#define KP2  256
#define NNN1 (BB*KP1)   // 32768
#define NNN2 (BB*KP2)   // 16384
#define NMASK (N0-1)
#define SLOT 64
#define SMSK (SLOT-1)

// padded smem leading dims (conflict-free fragment loads)
#define ALD 40
#define BLD 136

// -------- persistent device scratch (only ever referenced from device code) --------
__device__ float g_lin[N0*FH];
__device__ float g_fa[N0*FH];
__device__ float g_score[N0];
__device__ float g_gate1[NNN1];
__device__ float g_gate2[NNN2];
__device__ float g_z[BB*2*FH];
__device__ int   g_cntA[N0];
__device__ int   g_cntB[NNN1];
__device__ int   g_bktA[N0*SLOT];
__device__ int   g_bktB[NNN1*SLOT];
__device__ int   g_map[N0];
__device__ int   g_map2[NNN1];
__device__ int   g_sel1[NNN1];
__device__ int   g_sel2[NNN2];
__device__ __nv_bfloat16 g_wh[3*16384];   // W hi, bf16, [stage][k][n] row-major
__device__ __nv_bfloat16 g_wl[3*16384];   // W lo

__device__ __forceinline__ float bf16_round(float x) {
    return __bfloat162float(__float2bfloat16_rn(x));
}

// ---------------- init ----------------
__global__ void k_init() {
    int i = blockIdx.x * 256 + threadIdx.x;
    g_cntA[i] = 0;
    if (i < NNN1) g_cntB[i] = 0;
    if (i < BB*2*FH) g_z[i] = 0.0f;
}

// ---------------- W prep: W -> bf16 hi/lo, plain [k][n] layout ----------------
__global__ void k_prepw(const float* __restrict__ W1, const float* __restrict__ W2,
                        const float* __restrict__ W3) {
    int idx = blockIdx.x * 256 + threadIdx.x;   // 3*16384 threads
    int stage = idx >> 14;
    int r = idx & 16383;                        // r = k*128+n
    const float* W = (stage == 0) ? W1 : (stage == 1) ? W2 : W3;
    float w = W[r];
    float h = bf16_round(w);
    g_wh[idx] = __float2bfloat16_rn(h);
    g_wl[idx] = __float2bfloat16_rn(w - h);
}

// ---------------- bucket builds ----------------
__global__ void k_build1(const int* __restrict__ ei) {
    int i = blockIdx.x * 256 + threadIdx.x;
    if (i >= EE) return;
    int s = ei[i] & NMASK;
    int d = ei[EE + i] & NMASK;
    int p = atomicAdd(&g_cntA[d], 1) & SMSK;
    g_bktA[((size_t)d << 6) | p] = s;
}
__global__ void k_build2(const int* __restrict__ ei) {
    int i = blockIdx.x * 256 + threadIdx.x;
    if (i < NNN2) g_cntA[i] = 0;
    if (i >= EE) return;
    int s = ei[i] & NMASK;
    int d = ei[EE + i] & NMASK;
    int ns = g_map[s], nd = g_map[d];
    if (ns >= 0 && nd >= 0) {
        int p = atomicAdd(&g_cntB[nd], 1) & SMSK;
        g_bktB[((size_t)nd << 6) | p] = ns;
    }
}
__global__ void k_build3() {
    int idx = blockIdx.x * 256 + threadIdx.x;
    int n2 = idx >> 6, j = idx & SMSK;
    int c = g_cntB[n2]; if (c > SLOT) c = SLOT;
    if (j >= c) return;
    int s2 = g_bktB[((size_t)n2 << 6) | j] & (NNN1 - 1);
    int ns = g_map2[s2], nd = g_map2[n2];
    if (ns >= 0 && nd >= 0) {
        int p = atomicAdd(&g_cntA[nd], 1) & SMSK;
        g_bktA[((size_t)nd << 6) | p] = ns;
    }
}

// ---------------- WMMA bf16x3 GEMM: g_lin[M,128] = A[M,128] @ W[128,128] ----------------
// hi@hi + lo@hi + hi@lo, fp32 acc. 4 warps, each computes 64x64 (mt=4, nt=4).
// Padded smem (ALD=40, BLD=136) -> conflict-free load_matrix_sync.
// GATHER=0: A=Aext; GATHER=1: row=g_fa[sel1]*gate1; GATHER=2: row=g_fa[sel2]*gate2.
template<int GATHER, int STAGE>
__global__ __launch_bounds__(128) void k_gemm_wmma(const float* __restrict__ Aext) {
    const __nv_bfloat16* __restrict__ Wh = g_wh + STAGE * 16384;   // device-side reference
    const __nv_bfloat16* __restrict__ Wl = g_wl + STAGE * 16384;
    __shared__ __nv_bfloat16 Ah[128][ALD], Al[128][ALD];   // 10KB each
    __shared__ __nv_bfloat16 Bh[32][BLD], Bl[32][BLD];     // 8.5KB each
    int tid = threadIdx.x;
    int w = tid >> 5;
    int wr = w >> 1, wc = w & 1;             // warp tile: rows [wr*64,+64), cols [wc*64,+64)
    size_t m0 = (size_t)blockIdx.x * 128;

    // A source row: one row per thread (32 floats per k-chunk)
    int m = tid;
    const float* arow;
    float gt = 1.0f;
    if (GATHER == 0) {
        arow = Aext + (m0 + m) * 128;
    } else if (GATHER == 1) {
        int i = (int)(m0 + m) & (NNN1 - 1);
        arow = (const float*)g_fa + ((size_t)(g_sel1[i] & NMASK) << 7);
        gt = g_gate1[i];
    } else {
        int i = (int)(m0 + m) & (NNN2 - 1);
        arow = (const float*)g_fa + ((size_t)(g_sel2[i] & (NNN1 - 1)) << 7);
        gt = g_gate2[i];
    }

    wmma::fragment<wmma::accumulator, 16, 16, 16, float> acc[4][4];
    #pragma unroll
    for (int mt = 0; mt < 4; mt++)
        #pragma unroll
        for (int nt = 0; nt < 4; nt++) wmma::fill_fragment(acc[mt][nt], 0.0f);

    for (int kc = 0; kc < 128; kc += 32) {
        // ---- stage A chunk: fp32 -> bf16 hi/lo (32 floats per thread) ----
        #pragma unroll
        for (int q = 0; q < 8; q++) {
            float4 v = *(const float4*)(arow + kc + q * 4);
            v.x *= gt; v.y *= gt; v.z *= gt; v.w *= gt;
            float hx = bf16_round(v.x), hy = bf16_round(v.y);
            float hz = bf16_round(v.z), hw = bf16_round(v.w);
            Ah[m][q*4 + 0] = __float2bfloat16_rn(hx);
            Ah[m][q*4 + 1] = __float2bfloat16_rn(hy);
            Ah[m][q*4 + 2] = __float2bfloat16_rn(hz);
            Ah[m][q*4 + 3] = __float2bfloat16_rn(hw);
            Al[m][q*4 + 0] = __float2bfloat16_rn(v.x - hx);
            Al[m][q*4 + 1] = __float2bfloat16_rn(v.y - hy);
            Al[m][q*4 + 2] = __float2bfloat16_rn(v.z - hz);
            Al[m][q*4 + 3] = __float2bfloat16_rn(v.w - hw);
        }
        // ---- stage B chunk: 32x128 hi/lo, contiguous uint4 copies ----
        #pragma unroll
        for (int it = 0; it < 4; it++) {
            int idx = tid * 8 + it * 1024;
            int bk = idx >> 7, bn = idx & 127;
            *(uint4*)&Bh[bk][bn] = *(const uint4*)(Wh + (size_t)(kc + bk) * 128 + bn);
            *(uint4*)&Bl[bk][bn] = *(const uint4*)(Wl + (size_t)(kc + bk) * 128 + bn);
        }
        __syncthreads();

        #pragma unroll
        for (int ks = 0; ks < 32; ks += 16) {
            wmma::fragment<wmma::matrix_a, 16, 16, 16, __nv_bfloat16, wmma::row_major> af[4];
            // ---- sub-pass 1: a_hi @ (b_hi, b_lo) ----
            #pragma unroll
            for (int mt = 0; mt < 4; mt++)
                wmma::load_matrix_sync(af[mt], &Ah[wr * 64 + mt * 16][ks], ALD);
            #pragma unroll
            for (int nt = 0; nt < 4; nt++) {
                wmma::fragment<wmma::matrix_b, 16, 16, 16, __nv_bfloat16, wmma::row_major> bh, bl;
                wmma::load_matrix_sync(bh, &Bh[ks][wc * 64 + nt * 16], BLD);
                wmma::load_matrix_sync(bl, &Bl[ks][wc * 64 + nt * 16], BLD);
                #pragma unroll
                for (int mt = 0; mt < 4; mt++) {
                    wmma::mma_sync(acc[mt][nt], af[mt], bh, acc[mt][nt]);
                    wmma::mma_sync(acc[mt][nt], af[mt], bl, acc[mt][nt]);
                }
            }
            // ---- sub-pass 2: a_lo @ b_hi (reuse af registers) ----
            #pragma unroll
            for (int mt = 0; mt < 4; mt++)
                wmma::load_matrix_sync(af[mt], &Al[wr * 64 + mt * 16][ks], ALD);
            #pragma unroll
            for (int nt = 0; nt < 4; nt++) {
                wmma::fragment<wmma::matrix_b, 16, 16, 16, __nv_bfloat16, wmma::row_major> bh;
                wmma::load_matrix_sync(bh, &Bh[ks][wc * 64 + nt * 16], BLD);
                #pragma unroll
                for (int mt = 0; mt < 4; mt++)
                    wmma::mma_sync(acc[mt][nt], af[mt], bh, acc[mt][nt]);
            }
        }
        __syncthreads();
    }

    #pragma unroll
    for (int mt = 0; mt < 4; mt++)
        #pragma unroll
        for (int nt = 0; nt < 4; nt++)
            wmma::store_matrix_sync(g_lin + (m0 + wr * 64 + mt * 16) * 128 + wc * 64 + nt * 16,
                                    acc[mt][nt], 128, wmma::mem_row_major);
}

// ---------------- GCN conv: aggregate + bias + score + relu (warp/node) ----------------
template<int WHICH>
__global__ void k_conv(const float* __restrict__ bias,
                       const float* __restrict__ ws,
                       int nnodes) {
    int warp = (blockIdx.x * blockDim.x + threadIdx.x) >> 5;
    int lane = threadIdx.x & 31;
    if (warp >= nnodes) return;
    int node = warp;
    const int* cnt = WHICH ? g_cntB : g_cntA;
    const int* bkt = WHICH ? g_bktB : g_bktA;
    int c = cnt[node]; if (c > SLOT) c = SLOT;
    float degd = (float)c + 1.0f;
    float rsd  = rsqrtf(degd);
    size_t base = (size_t)node << 6;
    float4 acc = make_float4(0.f, 0.f, 0.f, 0.f);

    for (int b = 0; b < c; b += 32) {
        int m = c - b; if (m > 32) m = 32;
        int  src = 0; float nrm = 0.f;
        if (lane < m) {
            src = bkt[base + b + lane] & NMASK;
            int cs = cnt[src]; if (cs > SLOT) cs = SLOT;
            nrm = rsd * rsqrtf((float)cs + 1.0f);
        }
        for (int e = 0; e < m; e++) {
            int   s  = __shfl_sync(0xffffffffu, src, e);
            float nm = __shfl_sync(0xffffffffu, nrm, e);
            float4 hv = *(const float4*)(g_lin + ((size_t)s << 7) + (lane << 2));
            acc.x += hv.x * nm; acc.y += hv.y * nm;
            acc.z += hv.z * nm; acc.w += hv.w * nm;
        }
    }
    float dinv = 1.0f / degd;
    float4 self = *(const float4*)(g_lin + ((size_t)node << 7) + (lane << 2));
    float4 bv   = *(const float4*)(bias + (lane << 2));
    float o0 = acc.x + self.x * dinv + bv.x;
    float o1 = acc.y + self.y * dinv + bv.y;
    float o2 = acc.z + self.z * dinv + bv.z;
    float o3 = acc.w + self.w * dinv + bv.w;
    float4 wv = *(const float4*)(ws + (lane << 2));
    float sc = o0 * wv.x + o1 * wv.y + o2 * wv.z + o3 * wv.w;
    #pragma unroll
    for (int off = 16; off; off >>= 1) sc += __shfl_xor_sync(0xffffffffu, sc, off);
    if (lane == 0) g_score[node] = sc;
    float4 r = make_float4(fmaxf(o0, 0.f), fmaxf(o1, 0.f), fmaxf(o2, 0.f), fmaxf(o3, 0.f));
    *(float4*)(g_fa + ((size_t)node << 7) + (lane << 2)) = r;
}

// ---------------- per-graph top-k via bitonic sort ----------------
template<int STAGE>
__global__ void k_topk(int n, int k) {
    __shared__ float s[1024];
    __shared__ int   id[1024];
    int g = blockIdx.x & (BB - 1);
    int half = n >> 1;
    int t = threadIdx.x & (half - 1);
    s[t] = g_score[(g * n + t) & NMASK];               id[t] = t;
    s[t + half] = g_score[(g * n + t + half) & NMASK]; id[t + half] = t + half;
    __syncthreads();
    for (int kk = 2; kk <= n; kk <<= 1) {
        for (int j = kk >> 1; j > 0; j >>= 1) {
            int i = ((t & ~(j - 1)) << 1) | (t & (j - 1));
            int p = i | j;
            bool up = ((i & kk) == 0);
            float a = s[i], b = s[p];
            if ((a > b) == up) {
                s[i] = b; s[p] = a;
                int tmp = id[i]; id[i] = id[p]; id[p] = tmp;
            }
            __syncthreads();
        }
    }
    for (int p = t; p < n; p += half) {
        int oldl = id[p] & (n - 1);
        int ng = -1;
        if (p >= n - k) {
            int j = n - 1 - p;
            ng = g * k + j;
            if (STAGE == 0) {
                g_sel1[ng & (NNN1-1)]  = g * n + oldl;
                g_gate1[ng & (NNN1-1)] = tanhf(s[p]);
            } else {
                g_sel2[ng & (NNN2-1)]  = g * n + oldl;
                g_gate2[ng & (NNN2-1)] = tanhf(s[p]);
            }
        }
        if (STAGE == 0) g_map[(g * n + oldl) & NMASK] = ng;
        else            g_map2[(g * n + oldl) & (NNN1-1)] = ng;
    }
}

// ---------------- readout with inline gather ----------------
template<int STAGE>
__global__ void k_readout(int k) {
    int g = blockIdx.x & (BB - 1), f = threadIdx.x & 127;
    float mx = -3.4e38f, sm = 0.f;
    for (int m = 0; m < k; m++) {
        float v;
        if (STAGE == 1) {
            int i = g * k + m;
            v = g_fa[((size_t)(g_sel1[i] & NMASK) << 7) + f] * g_gate1[i];
        } else if (STAGE == 2) {
            int i = g * k + m;
            v = g_fa[((size_t)(g_sel2[i] & (NNN1-1)) << 7) + f] * g_gate2[i];
        } else {
            v = g_fa[((size_t)(g * k + m) << 7) + f];
        }
        mx = fmaxf(mx, v);
        sm += v;
    }
    g_z[g * 256 + f]       += fmaxf(mx, 0.f);
    g_z[g * 256 + 128 + f] += fmaxf(sm * (1.0f / (float)k), 0.f);
}

// ---------------- MLP head + log_softmax ----------------
__global__ void k_mlp(const float* __restrict__ L1w, const float* __restrict__ L1b,
                      const float* __restrict__ L2w, const float* __restrict__ L2b,
                      const float* __restrict__ L3w, const float* __restrict__ L3b,
                      float* __restrict__ out) {
    int g = blockIdx.x & (BB - 1), t = threadIdx.x & 127;
    __shared__ float zr[256], y1[128], y2[64], y3[8], lse[1];
    zr[t]       = g_z[g * 256 + t];
    zr[t + 128] = g_z[g * 256 + 128 + t];
    __syncthreads();
    float a = L1b[t];
    for (int i = 0; i < 256; i++) a += zr[i] * L1w[i * 128 + t];
    y1[t] = fmaxf(a, 0.f);
    __syncthreads();
    if (t < 64) {
        float b = L2b[t];
        for (int i = 0; i < 128; i++) b += y1[i] * L2w[i * 64 + t];
        y2[t] = fmaxf(b, 0.f);
    }
    __syncthreads();
    if (t < CC) {
        float c = L3b[t];
        for (int i = 0; i < 64; i++) c += y2[i] * L3w[i * CC + t];
        y3[t] = c;
    }
    __syncthreads();
    if (t == 0) {
        float m = y3[0];
        for (int j = 1; j < CC; j++) m = fmaxf(m, y3[j]);
        float s = 0.f;
        for (int j = 0; j < CC; j++) s += expf(y3[j] - m);
        lse[0] = m + logf(s);
    }
    __syncthreads();
    if (t < CC) out[g * CC + t] = y3[t] - lse[0];
}

// ======================================================================
extern "C" void kernel_launch(void* const* d_in, const int* in_sizes, int n_in,
                              void* d_out, int out_size) {
    const float* x    = (const float*)d_in[0];
    const int*   ei32 = (const int*)d_in[1];
    const float* W1 = (const float*)d_in[3];
    const float* b1 = (const float*)d_in[4];
    const float* s1 = (const float*)d_in[5];
    const float* W2 = (const float*)d_in[6];
    const float* b2 = (const float*)d_in[7];
    const float* s2 = (const float*)d_in[8];
    const float* W3 = (const float*)d_in[9];
    const float* b3 = (const float*)d_in[10];
    const float* s3 = (const float*)d_in[11];
    const float* L1w = (const float*)d_in[12];
    const float* L1b = (const float*)d_in[13];
    const float* L2w = (const float*)d_in[14];
    const float* L2b = (const float*)d_in[15];
    const float* L3w = (const float*)d_in[16];
    const float* L3b = (const float*)d_in[17];
    float* out = (float*)d_out;

    k_init<<<256, 256>>>();
    k_prepw<<<192, 256>>>(W1, W2, W3);

    // ---- stage 1 ----
    k_build1<<<EE/256, 256>>>(ei32);
    k_gemm_wmma<0, 0><<<N0/128, 128>>>(x);
    k_conv<0><<<N0/8, 256>>>(b1, s1, N0);
    k_topk<0><<<BB, NPG/2>>>(NPG, KP1);
    k_readout<1><<<BB, 128>>>(KP1);

    // ---- stage 2 ----
    k_build2<<<EE/256, 256>>>(ei32);
    k_gemm_wmma<1, 1><<<NNN1/128, 128>>>(nullptr);
    k_conv<1><<<NNN1/8, 256>>>(b2, s2, NNN1);
    k_topk<1><<<BB, KP1/2>>>(KP1, KP2);
    k_readout<2><<<BB, 128>>>(KP2);

    // ---- stage 3 ----
    k_build3<<<(NNN1*SLOT)/256, 256>>>();
    k_gemm_wmma<2, 2><<<NNN2/128, 128>>>(nullptr);
    k_conv<0><<<NNN2/8, 256>>>(b3, s3, NNN2);
    k_readout<3><<<BB, 128>>>(KP2);

    // ---- head ----
    k_mlp<<<BB, 128>>>(L1w, L1b, L2w, L2b, L3w, L3b, out);
}

// round 17
// speedup vs baseline: 1.2879x; 1.0573x over previous
#include <cuda_runtime.h>
#include <cuda_bf16.h>
#include <mma.h>
#include <math.h>
#include <stdint.h>

using namespace nvcuda;

// Problem constants
#define BB   64
#define NPG  1024
#define FH   128
#define EE   1048576
#define CC   6
#define N0   (BB*NPG)   // 65536
#define KP1  512
#define KP2  256
#define NNN1 (BB*KP1)   // 32768
#define NNN2 (BB*KP2)   // 16384
#define NMASK (N0-1)
#define SLOT 64
#define SMSK (SLOT-1)

// padded smem leading dims (conflict-free fragment loads)
#define ALD 40
#define BLD 136

// -------- persistent device scratch (only ever referenced from device code) --------
__device__ float g_lin[N0*FH];
__device__ float g_fa[N0*FH];
__device__ float g_score[N0];
__device__ float g_gate1[NNN1];
__device__ float g_gate2[NNN2];
__device__ float g_z[BB*2*FH];
__device__ int   g_cntA[N0];
__device__ int   g_cntB[NNN1];
__device__ int   g_bktA[N0*SLOT];
__device__ int   g_bktB[NNN1*SLOT];
__device__ int   g_map[N0];
__device__ int   g_map2[NNN1];
__device__ int   g_sel1[NNN1];
__device__ int   g_sel2[NNN2];
__device__ __nv_bfloat16 g_wh[3*16384];   // W hi, bf16, [stage][k][n] row-major
__device__ __nv_bfloat16 g_wl[3*16384];   // W lo

__device__ __forceinline__ float bf16_round(float x) {
    return __bfloat162float(__float2bfloat16_rn(x));
}

// ---------------- init ----------------
__global__ void k_init() {
    int i = blockIdx.x * 256 + threadIdx.x;
    g_cntA[i] = 0;
    if (i < NNN1) g_cntB[i] = 0;
    if (i < BB*2*FH) g_z[i] = 0.0f;
}

// ---------------- W prep: W -> bf16 hi/lo, plain [k][n] layout ----------------
__global__ void k_prepw(const float* __restrict__ W1, const float* __restrict__ W2,
                        const float* __restrict__ W3) {
    int idx = blockIdx.x * 256 + threadIdx.x;   // 3*16384 threads
    int stage = idx >> 14;
    int r = idx & 16383;                        // r = k*128+n
    const float* W = (stage == 0) ? W1 : (stage == 1) ? W2 : W3;
    float w = W[r];
    float h = bf16_round(w);
    g_wh[idx] = __float2bfloat16_rn(h);
    g_wl[idx] = __float2bfloat16_rn(w - h);
}

// ---------------- bucket builds ----------------
__global__ void k_build1(const int* __restrict__ ei) {
    int i = blockIdx.x * 256 + threadIdx.x;
    if (i >= EE) return;
    int s = ei[i] & NMASK;
    int d = ei[EE + i] & NMASK;
    int p = atomicAdd(&g_cntA[d], 1) & SMSK;
    g_bktA[((size_t)d << 6) | p] = s;
}
__global__ void k_build2(const int* __restrict__ ei) {
    int i = blockIdx.x * 256 + threadIdx.x;
    if (i < NNN2) g_cntA[i] = 0;
    if (i >= EE) return;
    int s = ei[i] & NMASK;
    int d = ei[EE + i] & NMASK;
    int ns = g_map[s], nd = g_map[d];
    if (ns >= 0 && nd >= 0) {
        int p = atomicAdd(&g_cntB[nd], 1) & SMSK;
        g_bktB[((size_t)nd << 6) | p] = ns;
    }
}
__global__ void k_build3() {
    int idx = blockIdx.x * 256 + threadIdx.x;
    int n2 = idx >> 6, j = idx & SMSK;
    int c = g_cntB[n2]; if (c > SLOT) c = SLOT;
    if (j >= c) return;
    int s2 = g_bktB[((size_t)n2 << 6) | j] & (NNN1 - 1);
    int ns = g_map2[s2], nd = g_map2[n2];
    if (ns >= 0 && nd >= 0) {
        int p = atomicAdd(&g_cntA[nd], 1) & SMSK;
        g_bktA[((size_t)nd << 6) | p] = ns;
    }
}

// ---------------- WMMA bf16x3 GEMM: g_lin[M,128] = A[M,128] @ W[128,128] ----------------
// hi@hi + lo@hi + hi@lo, fp32 acc. 4 warps, each computes 64x64 (mt=4, nt=4).
// Padded smem (ALD=40, BLD=136) -> conflict-free load_matrix_sync.
// GATHER=0: A=Aext; GATHER=1: row=g_fa[sel1]*gate1; GATHER=2: row=g_fa[sel2]*gate2.
template<int GATHER, int STAGE>
__global__ __launch_bounds__(128) void k_gemm_wmma(const float* __restrict__ Aext) {
    const __nv_bfloat16* __restrict__ Wh = g_wh + STAGE * 16384;   // device-side reference
    const __nv_bfloat16* __restrict__ Wl = g_wl + STAGE * 16384;
    __shared__ __nv_bfloat16 Ah[128][ALD], Al[128][ALD];   // 10KB each
    __shared__ __nv_bfloat16 Bh[32][BLD], Bl[32][BLD];     // 8.5KB each
    int tid = threadIdx.x;
    int w = tid >> 5;
    int wr = w >> 1, wc = w & 1;             // warp tile: rows [wr*64,+64), cols [wc*64,+64)
    size_t m0 = (size_t)blockIdx.x * 128;

    // A source row: one row per thread (32 floats per k-chunk)
    int m = tid;
    const float* arow;
    float gt = 1.0f;
    if (GATHER == 0) {
        arow = Aext + (m0 + m) * 128;
    } else if (GATHER == 1) {
        int i = (int)(m0 + m) & (NNN1 - 1);
        arow = (const float*)g_fa + ((size_t)(g_sel1[i] & NMASK) << 7);
        gt = g_gate1[i];
    } else {
        int i = (int)(m0 + m) & (NNN2 - 1);
        arow = (const float*)g_fa + ((size_t)(g_sel2[i] & (NNN1 - 1)) << 7);
        gt = g_gate2[i];
    }

    wmma::fragment<wmma::accumulator, 16, 16, 16, float> acc[4][4];
    #pragma unroll
    for (int mt = 0; mt < 4; mt++)
        #pragma unroll
        for (int nt = 0; nt < 4; nt++) wmma::fill_fragment(acc[mt][nt], 0.0f);

    for (int kc = 0; kc < 128; kc += 32) {
        // ---- stage A chunk: fp32 -> bf16 hi/lo (32 floats per thread) ----
        #pragma unroll
        for (int q = 0; q < 8; q++) {
            float4 v = *(const float4*)(arow + kc + q * 4);
            v.x *= gt; v.y *= gt; v.z *= gt; v.w *= gt;
            float hx = bf16_round(v.x), hy = bf16_round(v.y);
            float hz = bf16_round(v.z), hw = bf16_round(v.w);
            Ah[m][q*4 + 0] = __float2bfloat16_rn(hx);
            Ah[m][q*4 + 1] = __float2bfloat16_rn(hy);
            Ah[m][q*4 + 2] = __float2bfloat16_rn(hz);
            Ah[m][q*4 + 3] = __float2bfloat16_rn(hw);
            Al[m][q*4 + 0] = __float2bfloat16_rn(v.x - hx);
            Al[m][q*4 + 1] = __float2bfloat16_rn(v.y - hy);
            Al[m][q*4 + 2] = __float2bfloat16_rn(v.z - hz);
            Al[m][q*4 + 3] = __float2bfloat16_rn(v.w - hw);
        }
        // ---- stage B chunk: 32x128 hi/lo, contiguous uint4 copies ----
        #pragma unroll
        for (int it = 0; it < 4; it++) {
            int idx = tid * 8 + it * 1024;
            int bk = idx >> 7, bn = idx & 127;
            *(uint4*)&Bh[bk][bn] = *(const uint4*)(Wh + (size_t)(kc + bk) * 128 + bn);
            *(uint4*)&Bl[bk][bn] = *(const uint4*)(Wl + (size_t)(kc + bk) * 128 + bn);
        }
        __syncthreads();

        #pragma unroll
        for (int ks = 0; ks < 32; ks += 16) {
            wmma::fragment<wmma::matrix_a, 16, 16, 16, __nv_bfloat16, wmma::row_major> af[4];
            // ---- sub-pass 1: a_hi @ (b_hi, b_lo) ----
            #pragma unroll
            for (int mt = 0; mt < 4; mt++)
                wmma::load_matrix_sync(af[mt], &Ah[wr * 64 + mt * 16][ks], ALD);
            #pragma unroll
            for (int nt = 0; nt < 4; nt++) {
                wmma::fragment<wmma::matrix_b, 16, 16, 16, __nv_bfloat16, wmma::row_major> bh, bl;
                wmma::load_matrix_sync(bh, &Bh[ks][wc * 64 + nt * 16], BLD);
                wmma::load_matrix_sync(bl, &Bl[ks][wc * 64 + nt * 16], BLD);
                #pragma unroll
                for (int mt = 0; mt < 4; mt++) {
                    wmma::mma_sync(acc[mt][nt], af[mt], bh, acc[mt][nt]);
                    wmma::mma_sync(acc[mt][nt], af[mt], bl, acc[mt][nt]);
                }
            }
            // ---- sub-pass 2: a_lo @ b_hi (reuse af registers) ----
            #pragma unroll
            for (int mt = 0; mt < 4; mt++)
                wmma::load_matrix_sync(af[mt], &Al[wr * 64 + mt * 16][ks], ALD);
            #pragma unroll
            for (int nt = 0; nt < 4; nt++) {
                wmma::fragment<wmma::matrix_b, 16, 16, 16, __nv_bfloat16, wmma::row_major> bh;
                wmma::load_matrix_sync(bh, &Bh[ks][wc * 64 + nt * 16], BLD);
                #pragma unroll
                for (int mt = 0; mt < 4; mt++)
                    wmma::mma_sync(acc[mt][nt], af[mt], bh, acc[mt][nt]);
            }
        }
        __syncthreads();
    }

    #pragma unroll
    for (int mt = 0; mt < 4; mt++)
        #pragma unroll
        for (int nt = 0; nt < 4; nt++)
            wmma::store_matrix_sync(g_lin + (m0 + wr * 64 + mt * 16) * 128 + wc * 64 + nt * 16,
                                    acc[mt][nt], 128, wmma::mem_row_major);
}

// ---------------- GCN conv: aggregate + bias + score + relu (warp/node) ----------------
template<int WHICH>
__global__ void k_conv(const float* __restrict__ bias,
                       const float* __restrict__ ws,
                       int nnodes) {
    int warp = (blockIdx.x * blockDim.x + threadIdx.x) >> 5;
    int lane = threadIdx.x & 31;
    if (warp >= nnodes) return;
    int node = warp;
    const int* cnt = WHICH ? g_cntB : g_cntA;
    const int* bkt = WHICH ? g_bktB : g_bktA;
    int c = cnt[node]; if (c > SLOT) c = SLOT;
    float degd = (float)c + 1.0f;
    float rsd  = rsqrtf(degd);
    size_t base = (size_t)node << 6;
    float4 acc = make_float4(0.f, 0.f, 0.f, 0.f);

    for (int b = 0; b < c; b += 32) {
        int m = c - b; if (m > 32) m = 32;
        int  src = 0; float nrm = 0.f;
        if (lane < m) {
            src = bkt[base + b + lane] & NMASK;
            int cs = cnt[src]; if (cs > SLOT) cs = SLOT;
            nrm = rsd * rsqrtf((float)cs + 1.0f);
        }
        for (int e = 0; e < m; e++) {
            int   s  = __shfl_sync(0xffffffffu, src, e);
            float nm = __shfl_sync(0xffffffffu, nrm, e);
            float4 hv = *(const float4*)(g_lin + ((size_t)s << 7) + (lane << 2));
            acc.x += hv.x * nm; acc.y += hv.y * nm;
            acc.z += hv.z * nm; acc.w += hv.w * nm;
        }
    }
    float dinv = 1.0f / degd;
    float4 self = *(const float4*)(g_lin + ((size_t)node << 7) + (lane << 2));
    float4 bv   = *(const float4*)(bias + (lane << 2));
    float o0 = acc.x + self.x * dinv + bv.x;
    float o1 = acc.y + self.y * dinv + bv.y;
    float o2 = acc.z + self.z * dinv + bv.z;
    float o3 = acc.w + self.w * dinv + bv.w;
    float4 wv = *(const float4*)(ws + (lane << 2));
    float sc = o0 * wv.x + o1 * wv.y + o2 * wv.z + o3 * wv.w;
    #pragma unroll
    for (int off = 16; off; off >>= 1) sc += __shfl_xor_sync(0xffffffffu, sc, off);
    if (lane == 0) g_score[node] = sc;
    float4 r = make_float4(fmaxf(o0, 0.f), fmaxf(o1, 0.f), fmaxf(o2, 0.f), fmaxf(o3, 0.f));
    *(float4*)(g_fa + ((size_t)node << 7) + (lane << 2)) = r;
}

// ---------------- per-graph top-k via bitonic sort ----------------
template<int STAGE>
__global__ void k_topk(int n, int k) {
    __shared__ float s[1024];
    __shared__ int   id[1024];
    int g = blockIdx.x & (BB - 1);
    int half = n >> 1;
    int t = threadIdx.x & (half - 1);
    s[t] = g_score[(g * n + t) & NMASK];               id[t] = t;
    s[t + half] = g_score[(g * n + t + half) & NMASK]; id[t + half] = t + half;
    __syncthreads();
    for (int kk = 2; kk <= n; kk <<= 1) {
        for (int j = kk >> 1; j > 0; j >>= 1) {
            int i = ((t & ~(j - 1)) << 1) | (t & (j - 1));
            int p = i | j;
            bool up = ((i & kk) == 0);
            float a = s[i], b = s[p];
            if ((a > b) == up) {
                s[i] = b; s[p] = a;
                int tmp = id[i]; id[i] = id[p]; id[p] = tmp;
            }
            __syncthreads();
        }
    }
    for (int p = t; p < n; p += half) {
        int oldl = id[p] & (n - 1);
        int ng = -1;
        if (p >= n - k) {
            int j = n - 1 - p;
            ng = g * k + j;
            if (STAGE == 0) {
                g_sel1[ng & (NNN1-1)]  = g * n + oldl;
                g_gate1[ng & (NNN1-1)] = tanhf(s[p]);
            } else {
                g_sel2[ng & (NNN2-1)]  = g * n + oldl;
                g_gate2[ng & (NNN2-1)] = tanhf(s[p]);
            }
        }
        if (STAGE == 0) g_map[(g * n + oldl) & NMASK] = ng;
        else            g_map2[(g * n + oldl) & (NNN1-1)] = ng;
    }
}

// ---------------- readout with inline gather ----------------
template<int STAGE>
__global__ void k_readout(int k) {
    int g = blockIdx.x & (BB - 1), f = threadIdx.x & 127;
    float mx = -3.4e38f, sm = 0.f;
    for (int m = 0; m < k; m++) {
        float v;
        if (STAGE == 1) {
            int i = g * k + m;
            v = g_fa[((size_t)(g_sel1[i] & NMASK) << 7) + f] * g_gate1[i];
        } else if (STAGE == 2) {
            int i = g * k + m;
            v = g_fa[((size_t)(g_sel2[i] & (NNN1-1)) << 7) + f] * g_gate2[i];
        } else {
            v = g_fa[((size_t)(g * k + m) << 7) + f];
        }
        mx = fmaxf(mx, v);
        sm += v;
    }
    g_z[g * 256 + f]       += fmaxf(mx, 0.f);
    g_z[g * 256 + 128 + f] += fmaxf(sm * (1.0f / (float)k), 0.f);
}

// ---------------- MLP head + log_softmax ----------------
__global__ void k_mlp(const float* __restrict__ L1w, const float* __restrict__ L1b,
                      const float* __restrict__ L2w, const float* __restrict__ L2b,
                      const float* __restrict__ L3w, const float* __restrict__ L3b,
                      float* __restrict__ out) {
    int g = blockIdx.x & (BB - 1), t = threadIdx.x & 127;
    __shared__ float zr[256], y1[128], y2[64], y3[8], lse[1];
    zr[t]       = g_z[g * 256 + t];
    zr[t + 128] = g_z[g * 256 + 128 + t];
    __syncthreads();
    float a = L1b[t];
    for (int i = 0; i < 256; i++) a += zr[i] * L1w[i * 128 + t];
    y1[t] = fmaxf(a, 0.f);
    __syncthreads();
    if (t < 64) {
        float b = L2b[t];
        for (int i = 0; i < 128; i++) b += y1[i] * L2w[i * 64 + t];
        y2[t] = fmaxf(b, 0.f);
    }
    __syncthreads();
    if (t < CC) {
        float c = L3b[t];
        for (int i = 0; i < 64; i++) c += y2[i] * L3w[i * CC + t];
        y3[t] = c;
    }
    __syncthreads();
    if (t == 0) {
        float m = y3[0];
        for (int j = 1; j < CC; j++) m = fmaxf(m, y3[j]);
        float s = 0.f;
        for (int j = 0; j < CC; j++) s += expf(y3[j] - m);
        lse[0] = m + logf(s);
    }
    __syncthreads();
    if (t < CC) out[g * CC + t] = y3[t] - lse[0];
}

// ======================================================================
extern "C" void kernel_launch(void* const* d_in, const int* in_sizes, int n_in,
                              void* d_out, int out_size) {
    const float* x    = (const float*)d_in[0];
    const int*   ei32 = (const int*)d_in[1];
    const float* W1 = (const float*)d_in[3];
    const float* b1 = (const float*)d_in[4];
    const float* s1 = (const float*)d_in[5];
    const float* W2 = (const float*)d_in[6];
    const float* b2 = (const float*)d_in[7];
    const float* s2 = (const float*)d_in[8];
    const float* W3 = (const float*)d_in[9];
    const float* b3 = (const float*)d_in[10];
    const float* s3 = (const float*)d_in[11];
    const float* L1w = (const float*)d_in[12];
    const float* L1b = (const float*)d_in[13];
    const float* L2w = (const float*)d_in[14];
    const float* L2b = (const float*)d_in[15];
    const float* L3w = (const float*)d_in[16];
    const float* L3b = (const float*)d_in[17];
    float* out = (float*)d_out;

    // side stream + events (created once, on the non-capture correctness call)
    static cudaStream_t sB = 0;
    static cudaEvent_t evF, evT1, evT2, evB1, evB2, evB3;
    if (!sB) {
        cudaStreamCreateWithFlags(&sB, cudaStreamNonBlocking);
        cudaEventCreateWithFlags(&evF,  cudaEventDisableTiming);
        cudaEventCreateWithFlags(&evT1, cudaEventDisableTiming);
        cudaEventCreateWithFlags(&evT2, cudaEventDisableTiming);
        cudaEventCreateWithFlags(&evB1, cudaEventDisableTiming);
        cudaEventCreateWithFlags(&evB2, cudaEventDisableTiming);
        cudaEventCreateWithFlags(&evB3, cudaEventDisableTiming);
    }

    // ---- fork: side chain does init + build1 while main does prepw + gemm1 ----
    cudaEventRecord(evF, 0);
    cudaStreamWaitEvent(sB, evF, 0);
    k_init<<<256, 256, 0, sB>>>();
    k_build1<<<EE/256, 256, 0, sB>>>(ei32);
    cudaEventRecord(evB1, sB);

    k_prepw<<<192, 256>>>(W1, W2, W3);
    k_gemm_wmma<0, 0><<<N0/128, 128>>>(x);
    cudaStreamWaitEvent(0, evB1, 0);
    k_conv<0><<<N0/8, 256>>>(b1, s1, N0);
    k_topk<0><<<BB, NPG/2>>>(NPG, KP1);
    cudaEventRecord(evT1, 0);

    // ---- stage 2: side does build2 + readout1 while main does gemm2 ----
    cudaStreamWaitEvent(sB, evT1, 0);
    k_build2<<<EE/256, 256, 0, sB>>>(ei32);
    k_readout<1><<<BB, 128, 0, sB>>>(KP1);
    cudaEventRecord(evB2, sB);

    k_gemm_wmma<1, 1><<<NNN1/128, 128>>>(nullptr);
    cudaStreamWaitEvent(0, evB2, 0);
    k_conv<1><<<NNN1/8, 256>>>(b2, s2, NNN1);
    k_topk<1><<<BB, KP1/2>>>(KP1, KP2);
    cudaEventRecord(evT2, 0);

    // ---- stage 3: side does build3 + readout2 while main does gemm3 ----
    cudaStreamWaitEvent(sB, evT2, 0);
    k_build3<<<(NNN1*SLOT)/256, 256, 0, sB>>>();
    k_readout<2><<<BB, 128, 0, sB>>>(KP2);
    cudaEventRecord(evB3, sB);

    k_gemm_wmma<2, 2><<<NNN2/128, 128>>>(nullptr);
    cudaStreamWaitEvent(0, evB3, 0);
    k_conv<0><<<NNN2/8, 256>>>(b3, s3, NNN2);
    k_readout<3><<<BB, 128>>>(KP2);

    // ---- head ----
    k_mlp<<<BB, 128>>>(L1w, L1b, L2w, L2b, L3w, L3b, out);
}